// round 13
// baseline (speedup 1.0000x reference)
#include <cuda_runtime.h>
#include <math.h>

#define NN 100000   // nodes
#define NE 500000   // edges
#define D  128      // in/out dim
#define A  64       // attn dim
#define NR 401      // rela vocab
#define NQ 64       // queries
#define NT 366      // tau table

#define STAB_B 782          // ceil(NN/128)
#define TAB_B  105
#define ZERO_B 256
#define HTAU_B 183
#define PREP_GRID (STAB_B + TAB_B + ZERO_B + HTAU_B)
#define NTILE128 782        // ceil(NN/128) tiles per matrix for epi
#define EPI_HALF 74         // blocks per matrix (grid 148)

typedef unsigned long long ull;
typedef unsigned int uint32;

// ---------------- device scratch ----------------
__device__ float g_agg [NN * D];
__device__ float g_aggs[NN * D];
__device__ float g_stab[NN * A];
__device__ float g_rattn[NR * A];
__device__ float g_qrattn[NQ * A];
__device__ float g_tattn[NT * A];
__device__ float g_htau [NT * D];
__device__ float g_alpha[NE];

// ---------------- f32x2 helpers (B300 FFMA2) ----------------
__device__ __forceinline__ ull dup2(float a) {
    ull r; asm("mov.b64 %0, {%1,%1};" : "=l"(r) : "f"(a)); return r;
}
__device__ __forceinline__ void ffma2(ull& acc, ull a, ull b) {
    asm("fma.rn.f32x2 %0, %1, %2, %0;" : "+l"(acc) : "l"(a), "l"(b));
}
__device__ __forceinline__ uint32 smem_u32(const void* p) {
    uint32 a;
    asm("{ .reg .u64 t; cvta.to.shared.u64 t, %1; cvt.u32.u64 %0, t; }" : "=r"(a) : "l"(p));
    return a;
}
__device__ __forceinline__ void cpa16(uint32 dst, const float* src, int srcbytes) {
    asm volatile("cp.async.cg.shared.global [%0], [%1], 16, %2;"
                 :: "r"(dst), "l"(src), "r"(srcbytes) : "memory");
}
#define CP_COMMIT() asm volatile("cp.async.commit_group;" ::: "memory")
#define CP_WAIT(n)  asm volatile("cp.async.wait_group %0;" :: "n"(n) : "memory")

// ============ fused prep: stab GEMM | small tables | zero | htau (unchanged) ============
__global__ void __launch_bounds__(256) prep_kernel(
    const float* __restrict__ hidden, const float* __restrict__ Ws,
    const float* __restrict__ rela,   const int*   __restrict__ q_rel,
    const float* __restrict__ Wr,     const float* __restrict__ Wtau,
    const float* __restrict__ Wqr,    const float* __restrict__ Wqr_b,
    const float* __restrict__ w1, const float* __restrict__ b1,
    const float* __restrict__ w2, const float* __restrict__ b2,
    const int* __restrict__ q_tau_p)
{
    extern __shared__ float sm[];
    int b = blockIdx.x;
    int tid = threadIdx.x;

    if (b < STAB_B) {
        float* Wsm = sm;               // 128*64 floats
        float* As  = sm + 128 * A;     // 128*132 floats
        for (int i = tid; i < 128 * A / 4; i += 256)
            reinterpret_cast<float4*>(Wsm)[i] = reinterpret_cast<const float4*>(Ws)[i];
        int rbase = b * 128;
#pragma unroll
        for (int i = 0; i < 16; i++) {
            int fid = tid + i * 256;
            int r = fid >> 5, c4 = fid & 31;
            float4 v = make_float4(0.f, 0.f, 0.f, 0.f);
            if (rbase + r < NN)
                v = __ldg(reinterpret_cast<const float4*>(hidden + (size_t)(rbase + r) * D) + c4);
            *reinterpret_cast<float4*>(&As[r * 132 + c4 * 4]) = v;
        }
        __syncthreads();
        int tx = tid & 15, ty = tid >> 4;
        int c0 = tx * 4, r0 = ty * 8;
        ull acc[8][2];
#pragma unroll
        for (int r = 0; r < 8; r++) { acc[r][0] = 0ull; acc[r][1] = 0ull; }
#pragma unroll 4
        for (int kk = 0; kk < 32; kk++) {
            int k0 = kk * 4;
            ulonglong2 w[4];
#pragma unroll
            for (int j = 0; j < 4; j++)
                w[j] = *reinterpret_cast<const ulonglong2*>(&Wsm[(k0 + j) * A + c0]);
            float4 a[8];
#pragma unroll
            for (int r = 0; r < 8; r++)
                a[r] = *reinterpret_cast<const float4*>(&As[(r0 + r) * 132 + k0]);
#pragma unroll
            for (int r = 0; r < 8; r++) {
                ull d;
                d = dup2(a[r].x); ffma2(acc[r][0], d, w[0].x); ffma2(acc[r][1], d, w[0].y);
                d = dup2(a[r].y); ffma2(acc[r][0], d, w[1].x); ffma2(acc[r][1], d, w[1].y);
                d = dup2(a[r].z); ffma2(acc[r][0], d, w[2].x); ffma2(acc[r][1], d, w[2].y);
                d = dup2(a[r].w); ffma2(acc[r][0], d, w[3].x); ffma2(acc[r][1], d, w[3].y);
            }
        }
#pragma unroll
        for (int r = 0; r < 8; r++) {
            int row = rbase + r0 + r;
            if (row < NN)
                *reinterpret_cast<ulonglong2*>(&g_stab[(size_t)row * A + c0]) =
                    make_ulonglong2(acc[r][0], acc[r][1]);
        }
        return;
    }
    b -= STAB_B;

    if (b < TAB_B) {
        float* Wsm = sm;
        float* rowbuf = sm + D * A;
        const float* src = nullptr; const float* W; const float* bias = nullptr;
        const int* gather = nullptr;
        float* out; int rows; int base; int nblk; bool comp_tau = false;
        if (b < 51)      { src = rela; W = Wr;   out = g_rattn;  rows = NR; base = 0;  nblk = 51; }
        else if (b < 97) { comp_tau = true; W = Wtau; out = g_tattn; rows = NT; base = 51; nblk = 46; }
        else             { src = rela; W = Wqr; bias = Wqr_b; gather = q_rel;
                           out = g_qrattn; rows = NQ; base = 97; nblk = 8; }

        for (int i = tid; i < D * A; i += 256) Wsm[i] = W[i];
        __syncthreads();
        int warp = tid >> 5, lane = tid & 31;
        float b0 = 0.f, b1v = 0.f;
        if (bias) { b0 = bias[2 * lane]; b1v = bias[2 * lane + 1]; }
        float qt = (float)__ldg(q_tau_p);
        int gwarp = (b - base) * 8 + warp;
        int nwarps = nblk * 8;
        for (int r = gwarp; r < rows; r += nwarps) {
            if (comp_tau) {
                float delta = (float)r - qt;
                float4 a1 = __ldg(reinterpret_cast<const float4*>(w1) + lane);
                float4 c1 = __ldg(reinterpret_cast<const float4*>(b1) + lane);
                float4 a2 = __ldg(reinterpret_cast<const float4*>(w2) + lane);
                float4 c2 = __ldg(reinterpret_cast<const float4*>(b2) + lane);
                float4 v;
                v.x = fmaf(a1.x, delta, c1.x) + sinf(fmaf(a2.x, delta, c2.x));
                v.y = fmaf(a1.y, delta, c1.y) + sinf(fmaf(a2.y, delta, c2.y));
                v.z = fmaf(a1.z, delta, c1.z) + sinf(fmaf(a2.z, delta, c2.z));
                v.w = fmaf(a1.w, delta, c1.w) + sinf(fmaf(a2.w, delta, c2.w));
                reinterpret_cast<float4*>(&rowbuf[warp * D])[lane] = v;
            } else {
                int srow = gather ? gather[r] : r;
                reinterpret_cast<float4*>(&rowbuf[warp * D])[lane] =
                    reinterpret_cast<const float4*>(src + (size_t)srow * D)[lane];
            }
            __syncwarp();
            float a0 = b0, a1s = b1v;
#pragma unroll 4
            for (int k = 0; k < D; k++) {
                float h = rowbuf[warp * D + k];
                float2 w = *reinterpret_cast<const float2*>(&Wsm[k * A + 2 * lane]);
                a0  = fmaf(h, w.x, a0);
                a1s = fmaf(h, w.y, a1s);
            }
            *reinterpret_cast<float2*>(&out[(size_t)r * A + 2 * lane]) = make_float2(a0, a1s);
            __syncwarp();
        }
        return;
    }
    b -= TAB_B;

    if (b < ZERO_B) {
        size_t i = (size_t)b * 256 + tid;
        size_t n4 = (size_t)NN * D / 4;
        size_t stride = (size_t)ZERO_B * 256;
        float4 z = make_float4(0.f, 0.f, 0.f, 0.f);
        for (size_t j = i; j < n4; j += stride) {
            reinterpret_cast<float4*>(g_agg)[j]  = z;
            reinterpret_cast<float4*>(g_aggs)[j] = z;
        }
        return;
    }
    b -= ZERO_B;

    // htau table
    int idx = b * 256 + tid;
    if (idx < NT * D) {
        int t = idx >> 7, d = idx & 127;
        float qt = (float)__ldg(q_tau_p);
        float delta = (float)t - qt;
        g_htau[idx] = fmaf(w1[d], delta, b1[d]) + sinf(fmaf(w2[d], delta, b2[d]));
    }
}

// ---------------- phase 1: attention alpha per edge ----------------
__global__ void alpha_kernel(const int* __restrict__ edges,
                             const float* __restrict__ w_alpha, const float* __restrict__ w_alpha_b,
                             const int* __restrict__ q_tau_p) {
    int gw = (blockIdx.x * blockDim.x + threadIdx.x) >> 5;
    int lane = threadIdx.x & 31;
    if (gw >= NE) return;
    const int* e = edges + (size_t)gw * 7;
    int ridx = __ldg(e + 0);
    int rel  = __ldg(e + 2);
    int tau  = __ldg(e + 4);
    int sub  = __ldg(e + 5);
    int qt = __ldg(q_tau_p);
    int t = (tau >= 0) ? tau : qt;

    float a0 = g_stab[(size_t)sub * A + lane]      + g_rattn[rel * A + lane]
             + g_qrattn[ridx * A + lane]           + g_tattn[t * A + lane];
    float a1 = g_stab[(size_t)sub * A + 32 + lane] + g_rattn[rel * A + 32 + lane]
             + g_qrattn[ridx * A + 32 + lane]      + g_tattn[t * A + 32 + lane];
    a0 = fmaxf(a0, 0.f);
    a1 = fmaxf(a1, 0.f);
    float p = fmaf(a0, __ldg(w_alpha + lane), a1 * __ldg(w_alpha + 32 + lane));
#pragma unroll
    for (int o = 16; o; o >>= 1) p += __shfl_xor_sync(0xffffffffu, p, o);
    if (lane == 0)
        g_alpha[gw] = 1.f / (1.f + expf(-(p + __ldg(w_alpha_b))));
}

// ---------------- phase 2: message scatter, split by d-half ----------------
// grid (NE/8, 2); warp per (edge, half). Lanes 0-15 RED alpha*m into g_agg,
// lanes 16-31 RED (1-alpha)*m into g_aggs (same m via broadcast loads).
__device__ __forceinline__ void red4(float* p, float4 v) {
    asm volatile("red.global.add.v4.f32 [%0], {%1,%2,%3,%4};"
                 :: "l"(p), "f"(v.x), "f"(v.y), "f"(v.z), "f"(v.w) : "memory");
}

__global__ void msg_kernel(const float* __restrict__ hidden, const int* __restrict__ edges,
                           const float* __restrict__ rela, const int* __restrict__ q_tau_p) {
    int gw = blockIdx.x * 8 + (threadIdx.x >> 5);
    int lane = threadIdx.x & 31;
    if (gw >= NE) return;
    const int* e = edges + (size_t)gw * 7;
    int rel  = __ldg(e + 2);
    int tau  = __ldg(e + 4);
    int sub  = __ldg(e + 5);
    int obj  = __ldg(e + 6);
    int qt = __ldg(q_tau_p);
    int t = (tau >= 0) ? tau : qt;

    int half = blockIdx.y;
    int c4 = (half << 4) + (lane & 15);        // float4 index within the 128-dim row

    float alpha = __ldg(g_alpha + gw);
    float4 hs = __ldg(reinterpret_cast<const float4*>(hidden + (size_t)sub * D) + c4);
    float4 hr = __ldg(reinterpret_cast<const float4*>(rela + (size_t)rel * D) + c4);
    float4 ht = *(reinterpret_cast<const float4*>(g_htau + (size_t)t * D) + c4);
    float4 m = make_float4(hs.x + hr.x + ht.x, hs.y + hr.y + ht.y,
                           hs.z + hr.z + ht.z, hs.w + hr.w + ht.w);
    float s = (lane < 16) ? alpha : (1.f - alpha);
    float4 v = make_float4(s * m.x, s * m.y, s * m.z, s * m.w);
    float* dst = ((lane < 16) ? g_agg : g_aggs) + (size_t)obj * D + c4 * 4;
    red4(dst, v);
}

// ---------------- epilogue GEMM: 8-row tiles + cp.async double buffering (unchanged) ----------------
__global__ void __launch_bounds__(256, 1) epi_kernel(const float* __restrict__ Wh,
                                                     const float* __restrict__ Whs,
                                                     float* __restrict__ out) {
    extern __shared__ float sm[];
    float* Wsm = sm;                   // 16384 floats
    float* Abuf[2] = { sm + 16384, sm + 16384 + 128 * 132 };
    int tid = threadIdx.x;
    int mat = (blockIdx.x >= EPI_HALF) ? 1 : 0;
    int bx  = blockIdx.x - mat * EPI_HALF;
    const float* W    = mat ? Whs : Wh;
    const float* Asrc = mat ? g_aggs : g_agg;
    size_t obase0 = mat ? (size_t)NN * D : 0;

    uint32 abase[2] = { smem_u32(Abuf[0]), smem_u32(Abuf[1]) };

    for (int i = tid; i < 16384 / 4; i += 256)
        reinterpret_cast<float4*>(Wsm)[i] = reinterpret_cast<const float4*>(W)[i];

    {
        int rbase = bx * 128;
#pragma unroll
        for (int i = 0; i < 16; i++) {
            int fid = tid + i * 256;
            int r = fid >> 5, c4 = fid & 31;
            const float* src = Asrc + (size_t)(rbase + r) * D + c4 * 4;
            int bytes = (rbase + r < NN) ? 16 : 0;
            cpa16(abase[0] + (uint32)(r * 132 + c4 * 4) * 4, src, bytes);
        }
        CP_COMMIT();
    }

    int tx = tid & 15, ty = tid >> 4;
    int clo = tx * 4, chi = 64 + tx * 4;
    int r0 = ty * 8;
    int cur = 0;

    for (int tile = bx; tile < NTILE128; tile += EPI_HALF) {
        int tnext = tile + EPI_HALF;
        if (tnext < NTILE128) {
            int rbase = tnext * 128;
#pragma unroll
            for (int i = 0; i < 16; i++) {
                int fid = tid + i * 256;
                int r = fid >> 5, c4 = fid & 31;
                const float* src = Asrc + (size_t)(rbase + r) * D + c4 * 4;
                int bytes = (rbase + r < NN) ? 16 : 0;
                cpa16(abase[cur ^ 1] + (uint32)(r * 132 + c4 * 4) * 4, src, bytes);
            }
            CP_COMMIT();
            CP_WAIT(1);
        } else {
            CP_WAIT(0);
        }
        __syncthreads();

        const float* As = Abuf[cur];
        ull acc[8][4];
#pragma unroll
        for (int r = 0; r < 8; r++) {
            acc[r][0] = 0ull; acc[r][1] = 0ull; acc[r][2] = 0ull; acc[r][3] = 0ull;
        }
#pragma unroll 2
        for (int kk = 0; kk < 32; kk++) {
            int k0 = kk * 4;
            float4 a[8];
#pragma unroll
            for (int r = 0; r < 8; r++)
                a[r] = *reinterpret_cast<const float4*>(&As[(r0 + r) * 132 + k0]);
#pragma unroll
            for (int j = 0; j < 4; j++) {
                ulonglong2 wl = *reinterpret_cast<const ulonglong2*>(&Wsm[(k0 + j) * 128 + clo]);
                ulonglong2 wh = *reinterpret_cast<const ulonglong2*>(&Wsm[(k0 + j) * 128 + chi]);
#pragma unroll
                for (int r = 0; r < 8; r++) {
                    float av = (j == 0) ? a[r].x : (j == 1) ? a[r].y : (j == 2) ? a[r].z : a[r].w;
                    ull d = dup2(av);
                    ffma2(acc[r][0], d, wl.x); ffma2(acc[r][1], d, wl.y);
                    ffma2(acc[r][2], d, wh.x); ffma2(acc[r][3], d, wh.y);
                }
            }
        }

        int rbase = tile * 128;
#pragma unroll
        for (int r = 0; r < 8; r++) {
            int row = rbase + r0 + r;
            if (row < NN) {
                float* op = out + obase0 + (size_t)row * D;
                *reinterpret_cast<ulonglong2*>(op + clo) = make_ulonglong2(acc[r][0], acc[r][1]);
                *reinterpret_cast<ulonglong2*>(op + chi) = make_ulonglong2(acc[r][2], acc[r][3]);
            }
        }
        __syncthreads();
        cur ^= 1;
    }
}

// ---------------- launch ----------------
extern "C" void kernel_launch(void* const* d_in, const int* in_sizes, int n_in,
                              void* d_out, int out_size) {
    const int*   q_rel     = (const int*)  d_in[1];
    const int*   q_tau     = (const int*)  d_in[2];
    const float* hidden    = (const float*)d_in[3];
    const int*   edges     = (const int*)  d_in[4];
    const float* rela      = (const float*)d_in[7];
    const float* Ws_w      = (const float*)d_in[8];
    const float* Wr_w      = (const float*)d_in[9];
    const float* Wqr_w     = (const float*)d_in[10];
    const float* Wqr_b     = (const float*)d_in[11];
    const float* Wtau_w    = (const float*)d_in[12];
    const float* w_alpha_w = (const float*)d_in[13];
    const float* w_alpha_b = (const float*)d_in[14];
    const float* W_h_w     = (const float*)d_in[15];
    const float* W_h_s_w   = (const float*)d_in[16];
    const float* wt1       = (const float*)d_in[17];
    const float* bt1       = (const float*)d_in[18];
    const float* wt2       = (const float*)d_in[19];
    const float* bt2       = (const float*)d_in[20];
    float* out = (float*)d_out;

    int prep_smem = (128 * A + 128 * 132) * (int)sizeof(float);       // 100352 B
    int epi_smem  = (16384 + 2 * 128 * 132) * (int)sizeof(float);     // 200704 B
    cudaFuncSetAttribute(prep_kernel, cudaFuncAttributeMaxDynamicSharedMemorySize, prep_smem);
    cudaFuncSetAttribute(epi_kernel,  cudaFuncAttributeMaxDynamicSharedMemorySize, epi_smem);

    prep_kernel<<<PREP_GRID, 256, prep_smem>>>(hidden, Ws_w, rela, q_rel,
                                               Wr_w, Wtau_w, Wqr_w, Wqr_b,
                                               wt1, bt1, wt2, bt2, q_tau);
    alpha_kernel<<<NE / 8, 256>>>(edges, w_alpha_w, w_alpha_b, q_tau);
    dim3 mgrid(NE / 8, 2);
    msg_kernel<<<mgrid, 256>>>(hidden, edges, rela, q_tau);
    epi_kernel<<<148, 256, epi_smem>>>(W_h_w, W_h_s_w, out);
}

// round 14
// speedup vs baseline: 1.7495x; 1.7495x over previous
#include <cuda_runtime.h>
#include <math.h>

#define NN 100000   // nodes
#define NE 500000   // edges
#define D  128      // in/out dim
#define A  64       // attn dim
#define NR 401      // rela vocab
#define NQ 64       // queries
#define NT 366      // tau table

#define STAB_B 782          // ceil(NN/128)
#define TAB_B  105
#define ZERO_B 256
#define HTAU_B 183
#define PREP_GRID (STAB_B + TAB_B + ZERO_B + HTAU_B)
#define NTILE128 782        // ceil(NN/128) tiles per matrix for epi
#define EPI_HALF 74         // blocks per matrix (grid 148)

typedef unsigned long long ull;
typedef unsigned int uint32;

// ---------------- device scratch ----------------
__device__ float g_agg [NN * D];
__device__ float g_aggs[NN * D];
__device__ float g_stab[NN * A];
__device__ float g_rattn[NR * A];
__device__ float g_qrattn[NQ * A];
__device__ float g_tattn[NT * A];
__device__ float g_htau [NT * D];

// ---------------- f32x2 helpers (B300 FFMA2) ----------------
__device__ __forceinline__ ull dup2(float a) {
    ull r; asm("mov.b64 %0, {%1,%1};" : "=l"(r) : "f"(a)); return r;
}
__device__ __forceinline__ void ffma2(ull& acc, ull a, ull b) {
    asm("fma.rn.f32x2 %0, %1, %2, %0;" : "+l"(acc) : "l"(a), "l"(b));
}
__device__ __forceinline__ uint32 smem_u32(const void* p) {
    uint32 a;
    asm("{ .reg .u64 t; cvta.to.shared.u64 t, %1; cvt.u32.u64 %0, t; }" : "=r"(a) : "l"(p));
    return a;
}
__device__ __forceinline__ void cpa16(uint32 dst, const float* src, int srcbytes) {
    asm volatile("cp.async.cg.shared.global [%0], [%1], 16, %2;"
                 :: "r"(dst), "l"(src), "r"(srcbytes) : "memory");
}
#define CP_COMMIT() asm volatile("cp.async.commit_group;" ::: "memory")
#define CP_WAIT(n)  asm volatile("cp.async.wait_group %0;" :: "n"(n) : "memory")

// ============ fused prep: stab GEMM | small tables | zero | htau ============
__global__ void __launch_bounds__(256) prep_kernel(
    const float* __restrict__ hidden, const float* __restrict__ Ws,
    const float* __restrict__ rela,   const int*   __restrict__ q_rel,
    const float* __restrict__ Wr,     const float* __restrict__ Wtau,
    const float* __restrict__ Wqr,    const float* __restrict__ Wqr_b,
    const float* __restrict__ w1, const float* __restrict__ b1,
    const float* __restrict__ w2, const float* __restrict__ b2,
    const int* __restrict__ q_tau_p)
{
    extern __shared__ float sm[];
    int b = blockIdx.x;
    int tid = threadIdx.x;

    if (b < STAB_B) {
        float* Wsm = sm;               // 128*64 floats
        float* As  = sm + 128 * A;     // 128*132 floats
        for (int i = tid; i < 128 * A / 4; i += 256)
            reinterpret_cast<float4*>(Wsm)[i] = reinterpret_cast<const float4*>(Ws)[i];
        int rbase = b * 128;
#pragma unroll
        for (int i = 0; i < 16; i++) {
            int fid = tid + i * 256;
            int r = fid >> 5, c4 = fid & 31;
            float4 v = make_float4(0.f, 0.f, 0.f, 0.f);
            if (rbase + r < NN)
                v = __ldg(reinterpret_cast<const float4*>(hidden + (size_t)(rbase + r) * D) + c4);
            *reinterpret_cast<float4*>(&As[r * 132 + c4 * 4]) = v;
        }
        __syncthreads();
        int tx = tid & 15, ty = tid >> 4;
        int c0 = tx * 4, r0 = ty * 8;
        ull acc[8][2];
#pragma unroll
        for (int r = 0; r < 8; r++) { acc[r][0] = 0ull; acc[r][1] = 0ull; }
#pragma unroll 4
        for (int kk = 0; kk < 32; kk++) {
            int k0 = kk * 4;
            ulonglong2 w[4];
#pragma unroll
            for (int j = 0; j < 4; j++)
                w[j] = *reinterpret_cast<const ulonglong2*>(&Wsm[(k0 + j) * A + c0]);
            float4 a[8];
#pragma unroll
            for (int r = 0; r < 8; r++)
                a[r] = *reinterpret_cast<const float4*>(&As[(r0 + r) * 132 + k0]);
#pragma unroll
            for (int r = 0; r < 8; r++) {
                ull d;
                d = dup2(a[r].x); ffma2(acc[r][0], d, w[0].x); ffma2(acc[r][1], d, w[0].y);
                d = dup2(a[r].y); ffma2(acc[r][0], d, w[1].x); ffma2(acc[r][1], d, w[1].y);
                d = dup2(a[r].z); ffma2(acc[r][0], d, w[2].x); ffma2(acc[r][1], d, w[2].y);
                d = dup2(a[r].w); ffma2(acc[r][0], d, w[3].x); ffma2(acc[r][1], d, w[3].y);
            }
        }
#pragma unroll
        for (int r = 0; r < 8; r++) {
            int row = rbase + r0 + r;
            if (row < NN)
                *reinterpret_cast<ulonglong2*>(&g_stab[(size_t)row * A + c0]) =
                    make_ulonglong2(acc[r][0], acc[r][1]);
        }
        return;
    }
    b -= STAB_B;

    if (b < TAB_B) {
        float* Wsm = sm;
        float* rowbuf = sm + D * A;
        const float* src = nullptr; const float* W; const float* bias = nullptr;
        const int* gather = nullptr;
        float* out; int rows; int base; int nblk; bool comp_tau = false;
        if (b < 51)      { src = rela; W = Wr;   out = g_rattn;  rows = NR; base = 0;  nblk = 51; }
        else if (b < 97) { comp_tau = true; W = Wtau; out = g_tattn; rows = NT; base = 51; nblk = 46; }
        else             { src = rela; W = Wqr; bias = Wqr_b; gather = q_rel;
                           out = g_qrattn; rows = NQ; base = 97; nblk = 8; }

        for (int i = tid; i < D * A; i += 256) Wsm[i] = W[i];
        __syncthreads();
        int warp = tid >> 5, lane = tid & 31;
        float b0 = 0.f, b1v = 0.f;
        if (bias) { b0 = bias[2 * lane]; b1v = bias[2 * lane + 1]; }
        float qt = (float)__ldg(q_tau_p);
        int gwarp = (b - base) * 8 + warp;
        int nwarps = nblk * 8;
        for (int r = gwarp; r < rows; r += nwarps) {
            if (comp_tau) {
                float delta = (float)r - qt;
                float4 a1 = __ldg(reinterpret_cast<const float4*>(w1) + lane);
                float4 c1 = __ldg(reinterpret_cast<const float4*>(b1) + lane);
                float4 a2 = __ldg(reinterpret_cast<const float4*>(w2) + lane);
                float4 c2 = __ldg(reinterpret_cast<const float4*>(b2) + lane);
                float4 v;
                v.x = fmaf(a1.x, delta, c1.x) + sinf(fmaf(a2.x, delta, c2.x));
                v.y = fmaf(a1.y, delta, c1.y) + sinf(fmaf(a2.y, delta, c2.y));
                v.z = fmaf(a1.z, delta, c1.z) + sinf(fmaf(a2.z, delta, c2.z));
                v.w = fmaf(a1.w, delta, c1.w) + sinf(fmaf(a2.w, delta, c2.w));
                reinterpret_cast<float4*>(&rowbuf[warp * D])[lane] = v;
            } else {
                int srow = gather ? gather[r] : r;
                reinterpret_cast<float4*>(&rowbuf[warp * D])[lane] =
                    reinterpret_cast<const float4*>(src + (size_t)srow * D)[lane];
            }
            __syncwarp();
            float a0 = b0, a1s = b1v;
#pragma unroll 4
            for (int k = 0; k < D; k++) {
                float h = rowbuf[warp * D + k];
                float2 w = *reinterpret_cast<const float2*>(&Wsm[k * A + 2 * lane]);
                a0  = fmaf(h, w.x, a0);
                a1s = fmaf(h, w.y, a1s);
            }
            *reinterpret_cast<float2*>(&out[(size_t)r * A + 2 * lane]) = make_float2(a0, a1s);
            __syncwarp();
        }
        return;
    }
    b -= TAB_B;

    if (b < ZERO_B) {
        size_t i = (size_t)b * 256 + tid;
        size_t n4 = (size_t)NN * D / 4;
        size_t stride = (size_t)ZERO_B * 256;
        float4 z = make_float4(0.f, 0.f, 0.f, 0.f);
        for (size_t j = i; j < n4; j += stride) {
            reinterpret_cast<float4*>(g_agg)[j]  = z;
            reinterpret_cast<float4*>(g_aggs)[j] = z;
        }
        return;
    }
    b -= ZERO_B;

    // htau table (used by edge kernel, which runs after prep)
    int idx = b * 256 + tid;
    if (idx < NT * D) {
        int t = idx >> 7, d = idx & 127;
        float qt = (float)__ldg(q_tau_p);
        float delta = (float)t - qt;
        g_htau[idx] = fmaf(w1[d], delta, b1[d]) + sinf(fmaf(w2[d], delta, b2[d]));
    }
}

// ---------------- edge scatter (fused, best-known) ----------------
__device__ __forceinline__ void red4(float* p, float4 v) {
    asm volatile("red.global.add.v4.f32 [%0], {%1,%2,%3,%4};"
                 :: "l"(p), "f"(v.x), "f"(v.y), "f"(v.z), "f"(v.w) : "memory");
}

__global__ void edge_kernel(const float* __restrict__ hidden, const int* __restrict__ edges,
                            const float* __restrict__ rela,
                            const float* __restrict__ w_alpha, const float* __restrict__ w_alpha_b,
                            const int* __restrict__ q_tau_p) {
    int gw = (blockIdx.x * blockDim.x + threadIdx.x) >> 5;
    int lane = threadIdx.x & 31;
    if (gw >= NE) return;
    const int* e = edges + (size_t)gw * 7;
    int ridx = __ldg(e + 0);
    int rel  = __ldg(e + 2);
    int tau  = __ldg(e + 4);
    int sub  = __ldg(e + 5);
    int obj  = __ldg(e + 6);
    int qt = __ldg(q_tau_p);
    int t = (tau >= 0) ? tau : qt;

    float a0 = g_stab[(size_t)sub * A + lane]      + g_rattn[rel * A + lane]
             + g_qrattn[ridx * A + lane]           + g_tattn[t * A + lane];
    float a1 = g_stab[(size_t)sub * A + 32 + lane] + g_rattn[rel * A + 32 + lane]
             + g_qrattn[ridx * A + 32 + lane]      + g_tattn[t * A + 32 + lane];
    a0 = fmaxf(a0, 0.f);
    a1 = fmaxf(a1, 0.f);
    float p = fmaf(a0, __ldg(w_alpha + lane), a1 * __ldg(w_alpha + 32 + lane));
#pragma unroll
    for (int o = 16; o; o >>= 1) p += __shfl_xor_sync(0xffffffffu, p, o);
    float alpha = 1.f / (1.f + expf(-(p + __ldg(w_alpha_b))));
    float oma = 1.f - alpha;

    float4 hs = __ldg(reinterpret_cast<const float4*>(hidden + (size_t)sub * D) + lane);
    float4 hr = __ldg(reinterpret_cast<const float4*>(rela + (size_t)rel * D) + lane);
    float4 ht = *(reinterpret_cast<const float4*>(g_htau + (size_t)t * D) + lane);
    float4 m = make_float4(hs.x + hr.x + ht.x, hs.y + hr.y + ht.y,
                           hs.z + hr.z + ht.z, hs.w + hr.w + ht.w);
    float4 mm = make_float4(alpha * m.x, alpha * m.y, alpha * m.z, alpha * m.w);
    float4 ms = make_float4(oma * m.x, oma * m.y, oma * m.z, oma * m.w);

    red4(g_agg  + (size_t)obj * D + lane * 4, mm);
    red4(g_aggs + (size_t)obj * D + lane * 4, ms);
}

// ---------------- epilogue GEMM: 8-row tiles + cp.async double buffering ----------------
// grid 148: blocks [0,74) -> agg@Wh -> out[0:NN]; [74,148) -> aggs@Whs -> out[NN:2NN].
// 128-row A tiles double-buffered; 256 threads, thread = 8r x (4+4)c conflict-free.
// smem = 64KB (W) + 2 x 67.6KB (A) = 199.7KB.
__global__ void __launch_bounds__(256, 1) epi_kernel(const float* __restrict__ Wh,
                                                     const float* __restrict__ Whs,
                                                     float* __restrict__ out) {
    extern __shared__ float sm[];
    float* Wsm = sm;                   // 16384 floats
    float* Abuf[2] = { sm + 16384, sm + 16384 + 128 * 132 };
    int tid = threadIdx.x;
    int mat = (blockIdx.x >= EPI_HALF) ? 1 : 0;
    int bx  = blockIdx.x - mat * EPI_HALF;
    const float* W    = mat ? Whs : Wh;
    const float* Asrc = mat ? g_aggs : g_agg;
    size_t obase0 = mat ? (size_t)NN * D : 0;

    uint32 abase[2] = { smem_u32(Abuf[0]), smem_u32(Abuf[1]) };

    // W -> smem (plain loads; visible after first __syncthreads)
    for (int i = tid; i < 16384 / 4; i += 256)
        reinterpret_cast<float4*>(Wsm)[i] = reinterpret_cast<const float4*>(W)[i];

    // prefetch tile bx into buffer 0 (16 cp.async per thread)
    {
        int rbase = bx * 128;
#pragma unroll
        for (int i = 0; i < 16; i++) {
            int fid = tid + i * 256;                 // 16*256 = 4096 = 128*32
            int r = fid >> 5, c4 = fid & 31;
            const float* src = Asrc + (size_t)(rbase + r) * D + c4 * 4;
            int bytes = (rbase + r < NN) ? 16 : 0;
            cpa16(abase[0] + (uint32)(r * 132 + c4 * 4) * 4, src, bytes);
        }
        CP_COMMIT();
    }

    int tx = tid & 15, ty = tid >> 4;                // 16 col groups, 16 row groups
    int clo = tx * 4, chi = 64 + tx * 4;
    int r0 = ty * 8;
    int cur = 0;

    for (int tile = bx; tile < NTILE128; tile += EPI_HALF) {
        int tnext = tile + EPI_HALF;
        if (tnext < NTILE128) {
            int rbase = tnext * 128;
#pragma unroll
            for (int i = 0; i < 16; i++) {
                int fid = tid + i * 256;
                int r = fid >> 5, c4 = fid & 31;
                const float* src = Asrc + (size_t)(rbase + r) * D + c4 * 4;
                int bytes = (rbase + r < NN) ? 16 : 0;
                cpa16(abase[cur ^ 1] + (uint32)(r * 132 + c4 * 4) * 4, src, bytes);
            }
            CP_COMMIT();
            CP_WAIT(1);      // current buffer's group done; next still in flight
        } else {
            CP_WAIT(0);
        }
        __syncthreads();

        const float* As = Abuf[cur];
        ull acc[8][4];
#pragma unroll
        for (int r = 0; r < 8; r++) {
            acc[r][0] = 0ull; acc[r][1] = 0ull; acc[r][2] = 0ull; acc[r][3] = 0ull;
        }
#pragma unroll 2
        for (int kk = 0; kk < 32; kk++) {
            int k0 = kk * 4;
            float4 a[8];
#pragma unroll
            for (int r = 0; r < 8; r++)
                a[r] = *reinterpret_cast<const float4*>(&As[(r0 + r) * 132 + k0]);
#pragma unroll
            for (int j = 0; j < 4; j++) {
                ulonglong2 wl = *reinterpret_cast<const ulonglong2*>(&Wsm[(k0 + j) * 128 + clo]);
                ulonglong2 wh = *reinterpret_cast<const ulonglong2*>(&Wsm[(k0 + j) * 128 + chi]);
#pragma unroll
                for (int r = 0; r < 8; r++) {
                    float av = (j == 0) ? a[r].x : (j == 1) ? a[r].y : (j == 2) ? a[r].z : a[r].w;
                    ull d = dup2(av);
                    ffma2(acc[r][0], d, wl.x); ffma2(acc[r][1], d, wl.y);
                    ffma2(acc[r][2], d, wh.x); ffma2(acc[r][3], d, wh.y);
                }
            }
        }

        int rbase = tile * 128;
#pragma unroll
        for (int r = 0; r < 8; r++) {
            int row = rbase + r0 + r;
            if (row < NN) {
                float* op = out + obase0 + (size_t)row * D;
                *reinterpret_cast<ulonglong2*>(op + clo) = make_ulonglong2(acc[r][0], acc[r][1]);
                *reinterpret_cast<ulonglong2*>(op + chi) = make_ulonglong2(acc[r][2], acc[r][3]);
            }
        }
        __syncthreads();   // all reads of Abuf[cur] done before it is prefetched again
        cur ^= 1;
    }
}

// ---------------- launch ----------------
extern "C" void kernel_launch(void* const* d_in, const int* in_sizes, int n_in,
                              void* d_out, int out_size) {
    const int*   q_rel     = (const int*)  d_in[1];
    const int*   q_tau     = (const int*)  d_in[2];
    const float* hidden    = (const float*)d_in[3];
    const int*   edges     = (const int*)  d_in[4];
    const float* rela      = (const float*)d_in[7];
    const float* Ws_w      = (const float*)d_in[8];
    const float* Wr_w      = (const float*)d_in[9];
    const float* Wqr_w     = (const float*)d_in[10];
    const float* Wqr_b     = (const float*)d_in[11];
    const float* Wtau_w    = (const float*)d_in[12];
    const float* w_alpha_w = (const float*)d_in[13];
    const float* w_alpha_b = (const float*)d_in[14];
    const float* W_h_w     = (const float*)d_in[15];
    const float* W_h_s_w   = (const float*)d_in[16];
    const float* wt1       = (const float*)d_in[17];
    const float* bt1       = (const float*)d_in[18];
    const float* wt2       = (const float*)d_in[19];
    const float* bt2       = (const float*)d_in[20];
    float* out = (float*)d_out;

    int prep_smem = (128 * A + 128 * 132) * (int)sizeof(float);       // 100352 B
    int epi_smem  = (16384 + 2 * 128 * 132) * (int)sizeof(float);     // 200704 B
    cudaFuncSetAttribute(prep_kernel, cudaFuncAttributeMaxDynamicSharedMemorySize, prep_smem);
    cudaFuncSetAttribute(epi_kernel,  cudaFuncAttributeMaxDynamicSharedMemorySize, epi_smem);

    prep_kernel<<<PREP_GRID, 256, prep_smem>>>(hidden, Ws_w, rela, q_rel,
                                               Wr_w, Wtau_w, Wqr_w, Wqr_b,
                                               wt1, bt1, wt2, bt2, q_tau);
    edge_kernel<<<NE / 8, 256>>>(hidden, edges, rela, w_alpha_w, w_alpha_b, q_tau);
    epi_kernel<<<148, 256, epi_smem>>>(W_h_w, W_h_s_w, out);
}

// round 15
// speedup vs baseline: 1.7916x; 1.0240x over previous
#include <cuda_runtime.h>
#include <math.h>

#define NN 100000   // nodes
#define NE 500000   // edges
#define D  128      // in/out dim
#define A  64       // attn dim
#define NR 401      // rela vocab
#define NQ 64       // queries
#define NT 366      // tau table

#define ZERO_B 256
#define STAB_B 782          // ceil(NN/128)
#define TAB_B  105
#define HTAU_B 183
#define PREP_GRID (ZERO_B + STAB_B + TAB_B + HTAU_B)
#define NTILE128 782        // ceil(NN/128) tiles per matrix for epi
#define EPI_HALF 74         // blocks per matrix (grid 148)

typedef unsigned long long ull;
typedef unsigned int uint32;

// ---------------- device scratch ----------------
__device__ float g_agg [NN * D];
__device__ float g_aggs[NN * D];
__device__ float g_stab[NN * A];
__device__ float g_rattn[NR * A];
__device__ float g_qrattn[NQ * A];
__device__ float g_tattn[NT * A];
__device__ float g_htau [NT * D];

// ---------------- f32x2 helpers (B300 FFMA2) ----------------
__device__ __forceinline__ ull dup2(float a) {
    ull r; asm("mov.b64 %0, {%1,%1};" : "=l"(r) : "f"(a)); return r;
}
__device__ __forceinline__ void ffma2(ull& acc, ull a, ull b) {
    asm("fma.rn.f32x2 %0, %1, %2, %0;" : "+l"(acc) : "l"(a), "l"(b));
}
__device__ __forceinline__ uint32 smem_u32(const void* p) {
    uint32 a;
    asm("{ .reg .u64 t; cvta.to.shared.u64 t, %1; cvt.u32.u64 %0, t; }" : "=r"(a) : "l"(p));
    return a;
}
__device__ __forceinline__ void cpa16(uint32 dst, const float* src, int srcbytes) {
    asm volatile("cp.async.cg.shared.global [%0], [%1], 16, %2;"
                 :: "r"(dst), "l"(src), "r"(srcbytes) : "memory");
}
#define CP_COMMIT() asm volatile("cp.async.commit_group;" ::: "memory")
#define CP_WAIT(n)  asm volatile("cp.async.wait_group %0;" :: "n"(n) : "memory")

// ============ fused prep: zero | stab GEMM | small tables | htau ============
// ZERO first: DRAM-write-bound blocks start in wave 1, overlapping later FMA waves.
__global__ void __launch_bounds__(256) prep_kernel(
    const float* __restrict__ hidden, const float* __restrict__ Ws,
    const float* __restrict__ rela,   const int*   __restrict__ q_rel,
    const float* __restrict__ Wr,     const float* __restrict__ Wtau,
    const float* __restrict__ Wqr,    const float* __restrict__ Wqr_b,
    const float* __restrict__ w1, const float* __restrict__ b1,
    const float* __restrict__ w2, const float* __restrict__ b2,
    const int* __restrict__ q_tau_p)
{
    extern __shared__ float sm[];
    int b = blockIdx.x;
    int tid = threadIdx.x;

    if (b < ZERO_B) {
        size_t i = (size_t)b * 256 + tid;
        size_t n4 = (size_t)NN * D / 4;
        size_t stride = (size_t)ZERO_B * 256;
        float4 z = make_float4(0.f, 0.f, 0.f, 0.f);
        for (size_t j = i; j < n4; j += stride) {
            reinterpret_cast<float4*>(g_agg)[j]  = z;
            reinterpret_cast<float4*>(g_aggs)[j] = z;
        }
        return;
    }
    b -= ZERO_B;

    if (b < STAB_B) {
        float* Wsm = sm;               // 128*64 floats
        float* As  = sm + 128 * A;     // 128*132 floats
        for (int i = tid; i < 128 * A / 4; i += 256)
            reinterpret_cast<float4*>(Wsm)[i] = reinterpret_cast<const float4*>(Ws)[i];
        int rbase = b * 128;
#pragma unroll
        for (int i = 0; i < 16; i++) {
            int fid = tid + i * 256;
            int r = fid >> 5, c4 = fid & 31;
            float4 v = make_float4(0.f, 0.f, 0.f, 0.f);
            if (rbase + r < NN)
                v = __ldg(reinterpret_cast<const float4*>(hidden + (size_t)(rbase + r) * D) + c4);
            *reinterpret_cast<float4*>(&As[r * 132 + c4 * 4]) = v;
        }
        __syncthreads();
        int tx = tid & 15, ty = tid >> 4;
        int c0 = tx * 4, r0 = ty * 8;
        ull acc[8][2];
#pragma unroll
        for (int r = 0; r < 8; r++) { acc[r][0] = 0ull; acc[r][1] = 0ull; }
#pragma unroll 4
        for (int kk = 0; kk < 32; kk++) {
            int k0 = kk * 4;
            ulonglong2 w[4];
#pragma unroll
            for (int j = 0; j < 4; j++)
                w[j] = *reinterpret_cast<const ulonglong2*>(&Wsm[(k0 + j) * A + c0]);
            float4 a[8];
#pragma unroll
            for (int r = 0; r < 8; r++)
                a[r] = *reinterpret_cast<const float4*>(&As[(r0 + r) * 132 + k0]);
#pragma unroll
            for (int r = 0; r < 8; r++) {
                ull d;
                d = dup2(a[r].x); ffma2(acc[r][0], d, w[0].x); ffma2(acc[r][1], d, w[0].y);
                d = dup2(a[r].y); ffma2(acc[r][0], d, w[1].x); ffma2(acc[r][1], d, w[1].y);
                d = dup2(a[r].z); ffma2(acc[r][0], d, w[2].x); ffma2(acc[r][1], d, w[2].y);
                d = dup2(a[r].w); ffma2(acc[r][0], d, w[3].x); ffma2(acc[r][1], d, w[3].y);
            }
        }
#pragma unroll
        for (int r = 0; r < 8; r++) {
            int row = rbase + r0 + r;
            if (row < NN)
                *reinterpret_cast<ulonglong2*>(&g_stab[(size_t)row * A + c0]) =
                    make_ulonglong2(acc[r][0], acc[r][1]);
        }
        return;
    }
    b -= STAB_B;

    if (b < TAB_B) {
        float* Wsm = sm;
        float* rowbuf = sm + D * A;
        const float* src = nullptr; const float* W; const float* bias = nullptr;
        const int* gather = nullptr;
        float* out; int rows; int base; int nblk; bool comp_tau = false;
        if (b < 51)      { src = rela; W = Wr;   out = g_rattn;  rows = NR; base = 0;  nblk = 51; }
        else if (b < 97) { comp_tau = true; W = Wtau; out = g_tattn; rows = NT; base = 51; nblk = 46; }
        else             { src = rela; W = Wqr; bias = Wqr_b; gather = q_rel;
                           out = g_qrattn; rows = NQ; base = 97; nblk = 8; }

        for (int i = tid; i < D * A; i += 256) Wsm[i] = W[i];
        __syncthreads();
        int warp = tid >> 5, lane = tid & 31;
        float b0 = 0.f, b1v = 0.f;
        if (bias) { b0 = bias[2 * lane]; b1v = bias[2 * lane + 1]; }
        float qt = (float)__ldg(q_tau_p);
        int gwarp = (b - base) * 8 + warp;
        int nwarps = nblk * 8;
        for (int r = gwarp; r < rows; r += nwarps) {
            if (comp_tau) {
                float delta = (float)r - qt;
                float4 a1 = __ldg(reinterpret_cast<const float4*>(w1) + lane);
                float4 c1 = __ldg(reinterpret_cast<const float4*>(b1) + lane);
                float4 a2 = __ldg(reinterpret_cast<const float4*>(w2) + lane);
                float4 c2 = __ldg(reinterpret_cast<const float4*>(b2) + lane);
                float4 v;
                v.x = fmaf(a1.x, delta, c1.x) + sinf(fmaf(a2.x, delta, c2.x));
                v.y = fmaf(a1.y, delta, c1.y) + sinf(fmaf(a2.y, delta, c2.y));
                v.z = fmaf(a1.z, delta, c1.z) + sinf(fmaf(a2.z, delta, c2.z));
                v.w = fmaf(a1.w, delta, c1.w) + sinf(fmaf(a2.w, delta, c2.w));
                reinterpret_cast<float4*>(&rowbuf[warp * D])[lane] = v;
            } else {
                int srow = gather ? gather[r] : r;
                reinterpret_cast<float4*>(&rowbuf[warp * D])[lane] =
                    reinterpret_cast<const float4*>(src + (size_t)srow * D)[lane];
            }
            __syncwarp();
            float a0 = b0, a1s = b1v;
#pragma unroll 4
            for (int k = 0; k < D; k++) {
                float h = rowbuf[warp * D + k];
                float2 w = *reinterpret_cast<const float2*>(&Wsm[k * A + 2 * lane]);
                a0  = fmaf(h, w.x, a0);
                a1s = fmaf(h, w.y, a1s);
            }
            *reinterpret_cast<float2*>(&out[(size_t)r * A + 2 * lane]) = make_float2(a0, a1s);
            __syncwarp();
        }
        return;
    }
    b -= TAB_B;

    // htau table (used by edge kernel, which runs after prep)
    int idx = b * 256 + tid;
    if (idx < NT * D) {
        int t = idx >> 7, d = idx & 127;
        float qt = (float)__ldg(q_tau_p);
        float delta = (float)t - qt;
        g_htau[idx] = fmaf(w1[d], delta, b1[d]) + sinf(fmaf(w2[d], delta, b2[d]));
    }
}

// ---------------- edge scatter: 2 edges per warp (ILP) ----------------
__device__ __forceinline__ void red4(float* p, float4 v) {
    asm volatile("red.global.add.v4.f32 [%0], {%1,%2,%3,%4};"
                 :: "l"(p), "f"(v.x), "f"(v.y), "f"(v.z), "f"(v.w) : "memory");
}

__global__ void edge_kernel(const float* __restrict__ hidden, const int* __restrict__ edges,
                            const float* __restrict__ rela,
                            const float* __restrict__ w_alpha, const float* __restrict__ w_alpha_b,
                            const int* __restrict__ q_tau_p) {
    int warp = (blockIdx.x * blockDim.x + threadIdx.x) >> 5;
    int lane = threadIdx.x & 31;
    int e0 = warp * 2;
    if (e0 >= NE) return;
    int qt = __ldg(q_tau_p);
    float wa0 = __ldg(w_alpha + lane), wa1 = __ldg(w_alpha + 32 + lane);
    float wb = __ldg(w_alpha_b);

    int ridx[2], rel[2], t[2], sub[2], obj[2];
    int ne = (e0 + 1 < NE) ? 2 : 1;
#pragma unroll
    for (int i = 0; i < 2; i++) {
        int eid = (i < ne) ? e0 + i : e0;
        const int* e = edges + (size_t)eid * 7;
        ridx[i] = __ldg(e + 0);
        rel[i]  = __ldg(e + 2);
        int tau = __ldg(e + 4);
        sub[i]  = __ldg(e + 5);
        obj[i]  = __ldg(e + 6);
        t[i] = (tau >= 0) ? tau : qt;
    }

    // attention for both edges (loads batched for MLP)
    float p01[2];
#pragma unroll
    for (int i = 0; i < 2; i++) {
        float a0 = g_stab[(size_t)sub[i] * A + lane]      + g_rattn[rel[i] * A + lane]
                 + g_qrattn[ridx[i] * A + lane]           + g_tattn[t[i] * A + lane];
        float a1 = g_stab[(size_t)sub[i] * A + 32 + lane] + g_rattn[rel[i] * A + 32 + lane]
                 + g_qrattn[ridx[i] * A + 32 + lane]      + g_tattn[t[i] * A + 32 + lane];
        a0 = fmaxf(a0, 0.f);
        a1 = fmaxf(a1, 0.f);
        p01[i] = fmaf(a0, wa0, a1 * wa1);
    }
#pragma unroll
    for (int o = 16; o; o >>= 1) {
        p01[0] += __shfl_xor_sync(0xffffffffu, p01[0], o);
        p01[1] += __shfl_xor_sync(0xffffffffu, p01[1], o);
    }

    // messages for both edges
    float4 hs[2], hr[2], ht[2];
#pragma unroll
    for (int i = 0; i < 2; i++) {
        hs[i] = __ldg(reinterpret_cast<const float4*>(hidden + (size_t)sub[i] * D) + lane);
        hr[i] = __ldg(reinterpret_cast<const float4*>(rela + (size_t)rel[i] * D) + lane);
        ht[i] = *(reinterpret_cast<const float4*>(g_htau + (size_t)t[i] * D) + lane);
    }
#pragma unroll
    for (int i = 0; i < 2; i++) {
        if (i >= ne) break;
        float alpha = 1.f / (1.f + expf(-(p01[i] + wb)));
        float oma = 1.f - alpha;
        float4 m = make_float4(hs[i].x + hr[i].x + ht[i].x, hs[i].y + hr[i].y + ht[i].y,
                               hs[i].z + hr[i].z + ht[i].z, hs[i].w + hr[i].w + ht[i].w);
        float4 mm = make_float4(alpha * m.x, alpha * m.y, alpha * m.z, alpha * m.w);
        float4 ms = make_float4(oma * m.x, oma * m.y, oma * m.z, oma * m.w);
        red4(g_agg  + (size_t)obj[i] * D + lane * 4, mm);
        red4(g_aggs + (size_t)obj[i] * D + lane * 4, ms);
    }
}

// ---------------- epilogue GEMM: 8-row tiles + cp.async double buffering ----------------
__global__ void __launch_bounds__(256, 1) epi_kernel(const float* __restrict__ Wh,
                                                     const float* __restrict__ Whs,
                                                     float* __restrict__ out) {
    extern __shared__ float sm[];
    float* Wsm = sm;                   // 16384 floats
    float* Abuf[2] = { sm + 16384, sm + 16384 + 128 * 132 };
    int tid = threadIdx.x;
    int mat = (blockIdx.x >= EPI_HALF) ? 1 : 0;
    int bx  = blockIdx.x - mat * EPI_HALF;
    const float* W    = mat ? Whs : Wh;
    const float* Asrc = mat ? g_aggs : g_agg;
    size_t obase0 = mat ? (size_t)NN * D : 0;

    uint32 abase[2] = { smem_u32(Abuf[0]), smem_u32(Abuf[1]) };

    for (int i = tid; i < 16384 / 4; i += 256)
        reinterpret_cast<float4*>(Wsm)[i] = reinterpret_cast<const float4*>(W)[i];

    {
        int rbase = bx * 128;
#pragma unroll
        for (int i = 0; i < 16; i++) {
            int fid = tid + i * 256;
            int r = fid >> 5, c4 = fid & 31;
            const float* src = Asrc + (size_t)(rbase + r) * D + c4 * 4;
            int bytes = (rbase + r < NN) ? 16 : 0;
            cpa16(abase[0] + (uint32)(r * 132 + c4 * 4) * 4, src, bytes);
        }
        CP_COMMIT();
    }

    int tx = tid & 15, ty = tid >> 4;
    int clo = tx * 4, chi = 64 + tx * 4;
    int r0 = ty * 8;
    int cur = 0;

    for (int tile = bx; tile < NTILE128; tile += EPI_HALF) {
        int tnext = tile + EPI_HALF;
        if (tnext < NTILE128) {
            int rbase = tnext * 128;
#pragma unroll
            for (int i = 0; i < 16; i++) {
                int fid = tid + i * 256;
                int r = fid >> 5, c4 = fid & 31;
                const float* src = Asrc + (size_t)(rbase + r) * D + c4 * 4;
                int bytes = (rbase + r < NN) ? 16 : 0;
                cpa16(abase[cur ^ 1] + (uint32)(r * 132 + c4 * 4) * 4, src, bytes);
            }
            CP_COMMIT();
            CP_WAIT(1);
        } else {
            CP_WAIT(0);
        }
        __syncthreads();

        const float* As = Abuf[cur];
        ull acc[8][4];
#pragma unroll
        for (int r = 0; r < 8; r++) {
            acc[r][0] = 0ull; acc[r][1] = 0ull; acc[r][2] = 0ull; acc[r][3] = 0ull;
        }
#pragma unroll 2
        for (int kk = 0; kk < 32; kk++) {
            int k0 = kk * 4;
            float4 a[8];
#pragma unroll
            for (int r = 0; r < 8; r++)
                a[r] = *reinterpret_cast<const float4*>(&As[(r0 + r) * 132 + k0]);
#pragma unroll
            for (int j = 0; j < 4; j++) {
                ulonglong2 wl = *reinterpret_cast<const ulonglong2*>(&Wsm[(k0 + j) * 128 + clo]);
                ulonglong2 wh = *reinterpret_cast<const ulonglong2*>(&Wsm[(k0 + j) * 128 + chi]);
#pragma unroll
                for (int r = 0; r < 8; r++) {
                    float av = (j == 0) ? a[r].x : (j == 1) ? a[r].y : (j == 2) ? a[r].z : a[r].w;
                    ull d = dup2(av);
                    ffma2(acc[r][0], d, wl.x); ffma2(acc[r][1], d, wl.y);
                    ffma2(acc[r][2], d, wh.x); ffma2(acc[r][3], d, wh.y);
                }
            }
        }

        int rbase = tile * 128;
#pragma unroll
        for (int r = 0; r < 8; r++) {
            int row = rbase + r0 + r;
            if (row < NN) {
                float* op = out + obase0 + (size_t)row * D;
                *reinterpret_cast<ulonglong2*>(op + clo) = make_ulonglong2(acc[r][0], acc[r][1]);
                *reinterpret_cast<ulonglong2*>(op + chi) = make_ulonglong2(acc[r][2], acc[r][3]);
            }
        }
        __syncthreads();
        cur ^= 1;
    }
}

// ---------------- launch ----------------
extern "C" void kernel_launch(void* const* d_in, const int* in_sizes, int n_in,
                              void* d_out, int out_size) {
    const int*   q_rel     = (const int*)  d_in[1];
    const int*   q_tau     = (const int*)  d_in[2];
    const float* hidden    = (const float*)d_in[3];
    const int*   edges     = (const int*)  d_in[4];
    const float* rela      = (const float*)d_in[7];
    const float* Ws_w      = (const float*)d_in[8];
    const float* Wr_w      = (const float*)d_in[9];
    const float* Wqr_w     = (const float*)d_in[10];
    const float* Wqr_b     = (const float*)d_in[11];
    const float* Wtau_w    = (const float*)d_in[12];
    const float* w_alpha_w = (const float*)d_in[13];
    const float* w_alpha_b = (const float*)d_in[14];
    const float* W_h_w     = (const float*)d_in[15];
    const float* W_h_s_w   = (const float*)d_in[16];
    const float* wt1       = (const float*)d_in[17];
    const float* bt1       = (const float*)d_in[18];
    const float* wt2       = (const float*)d_in[19];
    const float* bt2       = (const float*)d_in[20];
    float* out = (float*)d_out;

    int prep_smem = (128 * A + 128 * 132) * (int)sizeof(float);       // 100352 B
    int epi_smem  = (16384 + 2 * 128 * 132) * (int)sizeof(float);     // 200704 B
    cudaFuncSetAttribute(prep_kernel, cudaFuncAttributeMaxDynamicSharedMemorySize, prep_smem);
    cudaFuncSetAttribute(epi_kernel,  cudaFuncAttributeMaxDynamicSharedMemorySize, epi_smem);

    prep_kernel<<<PREP_GRID, 256, prep_smem>>>(hidden, Ws_w, rela, q_rel,
                                               Wr_w, Wtau_w, Wqr_w, Wqr_b,
                                               wt1, bt1, wt2, bt2, q_tau);
    // 2 edges per warp -> NE/2 warps -> /8 warps per block
    edge_kernel<<<NE / 16, 256>>>(hidden, edges, rela, w_alpha_w, w_alpha_b, q_tau);
    epi_kernel<<<148, 256, epi_smem>>>(W_h_w, W_h_s_w, out);
}